// round 13
// baseline (speedup 1.0000x reference)
#include <cuda_runtime.h>
#include <math.h>

#define Bb   128
#define Ss   1024
#define IND  256
#define MM   64
#define DD   128
#define OUTD 128
#define ROWS (Bb*Ss)   // 131072
#define SB   8         // scan steps staged per smem block
#define NBLK (Ss/SB)   // 128

typedef unsigned long long u64;

__device__ __forceinline__ u64 pk2(float lo, float hi) {
    u64 r; asm("mov.b64 %0,{%1,%2};" : "=l"(r) : "f"(lo), "f"(hi)); return r;
}
__device__ __forceinline__ void upk2(float& lo, float& hi, u64 v) {
    asm("mov.b64 {%0,%1},%2;" : "=f"(lo), "=f"(hi) : "l"(v));
}
__device__ __forceinline__ u64 fma2(u64 a, u64 b, u64 c) {
    u64 d; asm("fma.rn.f32x2 %0,%1,%2,%3;" : "=l"(d) : "l"(a), "l"(b), "l"(c)); return d;
}
__device__ __forceinline__ u64 mul2(u64 a, u64 b) {
    u64 d; asm("mul.rn.f32x2 %0,%1,%2;" : "=l"(d) : "l"(a), "l"(b)); return d;
}
__device__ __forceinline__ u64 add2(u64 a, u64 b) {
    u64 d; asm("add.rn.f32x2 %0,%1,%2;" : "=l"(d) : "l"(a), "l"(b)); return d;
}
__device__ __forceinline__ void cpa16(void* smem, const void* gmem) {
    unsigned s = (unsigned)__cvta_generic_to_shared(smem);
    asm volatile("cp.async.cg.shared.global [%0],[%1],16;\n" :: "r"(s), "l"(gmem) : "memory");
}
__device__ __forceinline__ void cpa_commit() {
    asm volatile("cp.async.commit_group;\n" ::: "memory");
}
template<int N> __device__ __forceinline__ void cpa_wait() {
    asm volatile("cp.async.wait_group %0;\n" :: "n"(N) : "memory");
}

// ---------------- scratch ----------------
__device__ __align__(16) float g_Wk2[IND*MM];
__device__ __align__(16) float g_bk2[MM];
// g_wd row layout (128 floats): q-major. dup-pair for m = mq*8 + 2q + h at q*32 + mq*4 + 2h
__device__ __align__(16) float g_wd[(size_t)ROWS*2*MM];   // 67MB
__device__ __align__(16) float g_ea[(size_t)ROWS*2*DD];   // interleaved {-sig pair, tanh pair} 134MB
__device__ __align__(16) float g_r[(size_t)ROWS*DD];      // read vectors 67MB

// ---------------- K0 ----------------
__global__ void k0_fold(const float* __restrict__ Wr, const float* __restrict__ br,
                        const float* __restrict__ Mk) {
    int gid = blockIdx.x * 256 + threadIdx.x;
    if (gid < IND*MM) {
        int i = gid >> 6, m = gid & 63;
        const float* wr = Wr + (size_t)i * DD;
        const float* mk = Mk + (size_t)m * DD;
        float s = 0.f;
        #pragma unroll 8
        for (int d = 0; d < DD; d++) s = fmaf(wr[d], mk[d], s);
        g_Wk2[i*MM + m] = s;
    } else if (gid < IND*MM + MM) {
        int m = gid - IND*MM;
        const float* mk = Mk + (size_t)m * DD;
        float s = 0.f;
        #pragma unroll 8
        for (int d = 0; d < DD; d++) s = fmaf(br[d], mk[d], s);
        g_bk2[m] = s;
    }
}

// ---------------- K1 fused: w=softmax(x@Wk2+bk2) q-major dup; v=x@Ww+bw -> {-sig, tanh} ----------------
// smem union: GEMM phase {As2 u64[16][130], Bw2 u64[16][32], Bv2 u64[16][64]} (28.9KB)
//             epilogue   {sC float[128][65], rmax[128], rinv[128]}            (34.3KB)
__global__ __launch_bounds__(256) void k1_fused(const float* __restrict__ x,
                                                const float* __restrict__ Ww,
                                                const float* __restrict__ bw) {
    __shared__ __align__(16) char sb[34816];
    u64 (*As2)[130] = (u64(*)[130])sb;                 // duplicated (a,a) per row
    u64 (*Bw2)[32]  = (u64(*)[32])(sb + 16640);
    u64 (*Bv2)[64]  = (u64(*)[64])(sb + 20736);
    float (*sC)[65] = (float(*)[65])sb;                // reused after GEMM
    float* rmax = (float*)(sb + 33280);
    float* rinv = (float*)(sb + 33792);

    int tid = threadIdx.x;
    int tx = tid & 15;
    int ty = tid >> 4;
    int rowBase = blockIdx.x * 128;

    u64 accw[8][2];
    u64 accv[8][4];
    #pragma unroll
    for (int i = 0; i < 8; i++) {
        accw[i][0] = accw[i][1] = 0ull;
        #pragma unroll
        for (int j = 0; j < 4; j++) accv[i][j] = 0ull;
    }

    for (int kb = 0; kb < IND; kb += 16) {
        // A tile (duplicated u64)
        #pragma unroll
        for (int it = 0; it < 2; it++) {
            int f4 = tid + it * 256;
            int row = f4 >> 2, kk4 = f4 & 3;
            float4 v = *(const float4*)(x + (size_t)(rowBase + row) * IND + kb + kk4 * 4);
            As2[kk4*4+0][row] = pk2(v.x, v.x);
            As2[kk4*4+1][row] = pk2(v.y, v.y);
            As2[kk4*4+2][row] = pk2(v.z, v.z);
            As2[kk4*4+3][row] = pk2(v.w, v.w);
        }
        // Bw tile
        {
            int k = tid >> 4, n4 = tid & 15;
            float4 v = *(const float4*)(g_Wk2 + (size_t)(kb + k) * MM + n4 * 4);
            Bw2[k][n4*2+0] = pk2(v.x, v.y);
            Bw2[k][n4*2+1] = pk2(v.z, v.w);
        }
        // Bv tile
        #pragma unroll
        for (int it = 0; it < 2; it++) {
            int f4 = tid + it * 256;
            int k = f4 >> 5, n4 = f4 & 31;
            float4 v = *(const float4*)(Ww + (size_t)(kb + k) * DD + n4 * 4);
            Bv2[k][n4*2+0] = pk2(v.x, v.y);
            Bv2[k][n4*2+1] = pk2(v.z, v.w);
        }
        __syncthreads();
        #pragma unroll
        for (int k = 0; k < 16; k++) {
            u64 rw0 = Bw2[k][tx];
            u64 rw1 = Bw2[k][tx + 16];
            u64 rv0 = Bv2[k][tx];
            u64 rv1 = Bv2[k][tx + 16];
            u64 rv2 = Bv2[k][tx + 32];
            u64 rv3 = Bv2[k][tx + 48];
            #pragma unroll
            for (int i = 0; i < 8; i++) {
                u64 a2 = As2[k][ty*8 + i];
                accw[i][0] = fma2(a2, rw0, accw[i][0]);
                accw[i][1] = fma2(a2, rw1, accw[i][1]);
                accv[i][0] = fma2(a2, rv0, accv[i][0]);
                accv[i][1] = fma2(a2, rv1, accv[i][1]);
                accv[i][2] = fma2(a2, rv2, accv[i][2]);
                accv[i][3] = fma2(a2, rv3, accv[i][3]);
            }
        }
        __syncthreads();
    }

    // ---- softmax epilogue (sC reuses GEMM smem; GEMM loop ended with sync) ----
    float accl[8][4];
    float b0 = g_bk2[2*tx], b1 = g_bk2[2*tx+1], b2 = g_bk2[2*tx+32], b3 = g_bk2[2*tx+33];
    #pragma unroll
    for (int i = 0; i < 8; i++) {
        float lo, hi;
        upk2(lo, hi, accw[i][0]);
        accl[i][0] = lo + b0; accl[i][1] = hi + b1;
        upk2(lo, hi, accw[i][1]);
        accl[i][2] = lo + b2; accl[i][3] = hi + b3;
        int row = ty*8 + i;
        sC[row][2*tx]    = accl[i][0];
        sC[row][2*tx+1]  = accl[i][1];
        sC[row][2*tx+32] = accl[i][2];
        sC[row][2*tx+33] = accl[i][3];
    }
    __syncthreads();
    {
        int row = tid >> 1, h = tid & 1;
        float mx = -1e30f;
        #pragma unroll 8
        for (int i = 0; i < 32; i++) mx = fmaxf(mx, sC[row][h*32 + i]);
        mx = fmaxf(mx, __shfl_xor_sync(0xffffffffu, mx, 1));
        float s = 0.f;
        #pragma unroll 8
        for (int i = 0; i < 32; i++) s += expf(sC[row][h*32 + i] - mx);
        s += __shfl_xor_sync(0xffffffffu, s, 1);
        if (!h) { rmax[row] = mx; rinv[row] = 1.f / s; }
    }
    __syncthreads();
    // q-major duplicated w store
    {
        int q0  = tx & 3;
        int mq0 = tx >> 2;
        int off = q0*32 + mq0*4;
        #pragma unroll
        for (int i = 0; i < 8; i++) {
            int row = ty*8 + i;
            float m = rmax[row], inv = rinv[row];
            float* wd = g_wd + (size_t)(rowBase + row) * (2*MM);
            float w0 = expf(accl[i][0]-m)*inv;
            float w1 = expf(accl[i][1]-m)*inv;
            float w2 = expf(accl[i][2]-m)*inv;
            float w3 = expf(accl[i][3]-m)*inv;
            float4 p0; p0.x = w0; p0.y = w0; p0.z = w1; p0.w = w1;
            float4 p1; p1.x = w2; p1.y = w2; p1.z = w3; p1.w = w3;
            *(float4*)(wd + off)      = p0;
            *(float4*)(wd + off + 16) = p1;
        }
    }
    // ---- ea epilogue (regs only) ----
    float blo[4], bhi[4];
    #pragma unroll
    for (int j = 0; j < 4; j++) {
        int c = 2*(tx + 16*j);
        blo[j] = bw[c]; bhi[j] = bw[c+1];
    }
    #pragma unroll
    for (int i = 0; i < 8; i++) {
        size_t row = (size_t)(rowBase + ty*8 + i);
        #pragma unroll
        for (int j = 0; j < 4; j++) {
            float lo, hi;
            upk2(lo, hi, accv[i][j]);
            float v0 = lo + blo[j], v1 = hi + bhi[j];
            int p = tx + 16*j;
            float4 eav;
            eav.x = -1.f/(1.f+expf(-v0));
            eav.y = -1.f/(1.f+expf(-v1));
            eav.z = tanhf(v0);
            eav.w = tanhf(v1);
            *(float4*)(g_ea + row*(2*DD) + 4*p) = eav;
        }
    }
}

// ---------------- K2: scan; smem-staged coefficients + explicit LDS register pipeline ----------------
__global__ __launch_bounds__(512) void k2_scan(const float* __restrict__ mv0) {
    __shared__ __align__(16) float sw[2][SB*128];    // 2 x 4KB
    __shared__ __align__(16) float sea[2][SB*256];   // 2 x 8KB

    int b = blockIdx.x;
    int tid = threadIdx.x;
    int warp = tid >> 5, lane = tid & 31;
    int dp = lane & 3, mq = lane >> 2;
    int d0 = warp * 8 + dp * 2;
    int m0 = mq * 8;

    const float* wsrc  = g_wd + (size_t)b * Ss * 128;
    const float* easrc = g_ea + (size_t)b * Ss * 256;
    float*       rp    = g_r  + (size_t)b * Ss * DD + d0;

    u64 Mv[8];
    #pragma unroll
    for (int j = 0; j < 8; j++)
        Mv[j] = *(const u64*)(mv0 + (size_t)(m0 + j) * DD + d0);

#define STAGE(BLK, BF) do { \
        const float4* ws = (const float4*)(wsrc  + (size_t)(BLK) * SB * 128); \
        const float4* es = (const float4*)(easrc + (size_t)(BLK) * SB * 256); \
        float4* wdst = (float4*)sw[BF]; \
        float4* edst = (float4*)sea[BF]; \
        if (tid < 256) cpa16(&wdst[tid], &ws[tid]); \
        cpa16(&edst[tid], &es[tid]); \
    } while (0)

    STAGE(0, 0); cpa_commit();
    STAGE(1, 1); cpa_commit();

    u64 rprev = 0ull;

    for (int blk = 0; blk < NBLK; blk++) {
        int bf = blk & 1;
        cpa_wait<1>();
        __syncthreads();

        const float* wbase  = sw[bf]  + mq * 4;
        const float* eabase = sea[bf] + (warp * 4 + dp) * 4;

        // register pipeline: coefficients for step s live in cq*/cea while s executes
        longlong2 cq0 = *(const longlong2*)(wbase +  0);
        longlong2 cq1 = *(const longlong2*)(wbase + 32);
        longlong2 cq2 = *(const longlong2*)(wbase + 64);
        longlong2 cq3 = *(const longlong2*)(wbase + 96);
        longlong2 cea = *(const longlong2*)(eabase);

        #pragma unroll
        for (int s = 0; s < SB; s++) {
            int t = blk * SB + s;
            longlong2 nq0, nq1, nq2, nq3, nea;
            if (s + 1 < SB) {
                const float* wrow = wbase + (s+1) * 128;
                nq0 = *(const longlong2*)(wrow +  0);
                nq1 = *(const longlong2*)(wrow + 32);
                nq2 = *(const longlong2*)(wrow + 64);
                nq3 = *(const longlong2*)(wrow + 96);
                nea = *(const longlong2*)(eabase + (s+1) * 256);
            }

            u64 en2 = (u64)cea.x;       // already negated sigmoid
            u64 a2c = (u64)cea.y;
            u64 wl0 = (u64)cq0.x, wl1 = (u64)cq0.y;
            u64 wl2 = (u64)cq1.x, wl3 = (u64)cq1.y;
            u64 wl4 = (u64)cq2.x, wl5 = (u64)cq2.y;
            u64 wl6 = (u64)cq3.x, wl7 = (u64)cq3.y;

            u64 r0, r1;
            {
                u64 t0 = mul2(wl0, Mv[0]); r0 = t0;
                Mv[0] = fma2(t0, en2, Mv[0]); Mv[0] = fma2(wl0, a2c, Mv[0]);
                u64 t1 = mul2(wl1, Mv[1]); r1 = t1;
                Mv[1] = fma2(t1, en2, Mv[1]); Mv[1] = fma2(wl1, a2c, Mv[1]);
                u64 t2 = mul2(wl2, Mv[2]); r0 = add2(r0, t2);
                Mv[2] = fma2(t2, en2, Mv[2]); Mv[2] = fma2(wl2, a2c, Mv[2]);
                u64 t3 = mul2(wl3, Mv[3]); r1 = add2(r1, t3);
                Mv[3] = fma2(t3, en2, Mv[3]); Mv[3] = fma2(wl3, a2c, Mv[3]);
                u64 t4 = mul2(wl4, Mv[4]); r0 = add2(r0, t4);
                Mv[4] = fma2(t4, en2, Mv[4]); Mv[4] = fma2(wl4, a2c, Mv[4]);
                u64 t5 = mul2(wl5, Mv[5]); r1 = add2(r1, t5);
                Mv[5] = fma2(t5, en2, Mv[5]); Mv[5] = fma2(wl5, a2c, Mv[5]);
                u64 t6 = mul2(wl6, Mv[6]); r0 = add2(r0, t6);
                Mv[6] = fma2(t6, en2, Mv[6]); Mv[6] = fma2(wl6, a2c, Mv[6]);
                u64 t7 = mul2(wl7, Mv[7]); r1 = add2(r1, t7);
                Mv[7] = fma2(t7, en2, Mv[7]); Mv[7] = fma2(wl7, a2c, Mv[7]);
            }
            // finalize PREVIOUS step's r
            {
                u64 p = rprev;
                p = add2(p, __shfl_xor_sync(0xffffffffu, p, 4));
                p = add2(p, __shfl_xor_sync(0xffffffffu, p, 8));
                p = add2(p, __shfl_xor_sync(0xffffffffu, p, 16));
                if (t > 0 && mq == 0)
                    *(u64*)(rp + (size_t)(t - 1) * DD) = p;
            }
            rprev = add2(r0, r1);

            if (s + 1 < SB) { cq0 = nq0; cq1 = nq1; cq2 = nq2; cq3 = nq3; cea = nea; }
        }

        __syncthreads();
        if (blk + 2 < NBLK) STAGE(blk + 2, bf);
        cpa_commit();
    }
    {
        u64 p = rprev;
        p = add2(p, __shfl_xor_sync(0xffffffffu, p, 4));
        p = add2(p, __shfl_xor_sync(0xffffffffu, p, 8));
        p = add2(p, __shfl_xor_sync(0xffffffffu, p, 16));
        if (mq == 0)
            *(u64*)(rp + (size_t)(Ss - 1) * DD) = p;
    }
#undef STAGE
}

// ---------------- K3: y = sigmoid(r @ Wp + bp); duplicated-A smem ----------------
__global__ __launch_bounds__(256) void k3_out(const float* __restrict__ Wp,
                                              const float* __restrict__ bp,
                                              float* __restrict__ out) {
    __shared__ __align__(16) u64 As2[16][130];
    __shared__ __align__(16) u64 Bs2[16][64];
    int tid = threadIdx.x;
    int tx = tid & 15;
    int ty = tid >> 4;
    int rowBase = blockIdx.x * 128;

    u64 acc2[8][4];
    #pragma unroll
    for (int i = 0; i < 8; i++)
        #pragma unroll
        for (int j = 0; j < 4; j++) acc2[i][j] = 0ull;

    for (int kb = 0; kb < DD; kb += 16) {
        #pragma unroll
        for (int it = 0; it < 2; it++) {
            int f4 = tid + it * 256;
            int row = f4 >> 2, kk4 = f4 & 3;
            float4 v = *(const float4*)(g_r + (size_t)(rowBase + row) * DD + kb + kk4 * 4);
            As2[kk4*4+0][row] = pk2(v.x, v.x);
            As2[kk4*4+1][row] = pk2(v.y, v.y);
            As2[kk4*4+2][row] = pk2(v.z, v.z);
            As2[kk4*4+3][row] = pk2(v.w, v.w);
        }
        #pragma unroll
        for (int it = 0; it < 2; it++) {
            int f4 = tid + it * 256;
            int k = f4 >> 5, n4 = f4 & 31;
            float4 v = *(const float4*)(Wp + (size_t)(kb + k) * OUTD + n4 * 4);
            Bs2[k][n4*2+0] = pk2(v.x, v.y);
            Bs2[k][n4*2+1] = pk2(v.z, v.w);
        }
        __syncthreads();
        #pragma unroll
        for (int k = 0; k < 16; k++) {
            u64 rb0 = Bs2[k][tx];
            u64 rb1 = Bs2[k][tx + 16];
            u64 rb2 = Bs2[k][tx + 32];
            u64 rb3 = Bs2[k][tx + 48];
            #pragma unroll
            for (int i = 0; i < 8; i++) {
                u64 a2 = As2[k][ty*8 + i];
                acc2[i][0] = fma2(a2, rb0, acc2[i][0]);
                acc2[i][1] = fma2(a2, rb1, acc2[i][1]);
                acc2[i][2] = fma2(a2, rb2, acc2[i][2]);
                acc2[i][3] = fma2(a2, rb3, acc2[i][3]);
            }
        }
        __syncthreads();
    }
    float blo[4], bhi[4];
    #pragma unroll
    for (int j = 0; j < 4; j++) {
        int c = 2*(tx + 16*j);
        blo[j] = bp[c]; bhi[j] = bp[c+1];
    }
    #pragma unroll
    for (int i = 0; i < 8; i++) {
        size_t row = (size_t)(rowBase + ty*8 + i);
        #pragma unroll
        for (int j = 0; j < 4; j++) {
            float lo, hi;
            upk2(lo, hi, acc2[i][j]);
            float v0 = lo + blo[j], v1 = hi + bhi[j];
            int c = 2*(tx + 16*j);
            *(u64*)(out + row*OUTD + c) = pk2(1.f/(1.f+expf(-v0)), 1.f/(1.f+expf(-v1)));
        }
    }
}

// ---------------- launch ----------------
extern "C" void kernel_launch(void* const* d_in, const int* in_sizes, int n_in,
                              void* d_out, int out_size) {
    const float* x   = (const float*)d_in[0];
    const float* Mk  = (const float*)d_in[1];
    const float* Mv0 = (const float*)d_in[2];
    const float* Wr  = (const float*)d_in[3];
    const float* br  = (const float*)d_in[4];
    const float* Ww  = (const float*)d_in[5];
    const float* bw  = (const float*)d_in[6];
    const float* Wp  = (const float*)d_in[7];
    const float* bp  = (const float*)d_in[8];
    float* out = (float*)d_out;

    k0_fold<<<65, 256>>>(Wr, br, Mk);
    k1_fused<<<ROWS/128, 256>>>(x, Ww, bw);
    k2_scan<<<Bb, 512>>>(Mv0);
    k3_out<<<ROWS/128, 256>>>(Wp, bp, out);
}